// round 6
// baseline (speedup 1.0000x reference)
#include <cuda_runtime.h>
#include <cuda_bf16.h>
#include <cstdint>
#include <math.h>

#define C 128
#define MAXN 100000
#define MAXE 1600000

// ---------------------------------------------------------------------------
// Scratch
// ---------------------------------------------------------------------------
__device__ int            g_deg[MAXN];
__device__ int            g_off[MAXN + 1];
__device__ int            g_cursor[MAXN];
__device__ int            g_csr_src[MAXE];
// A = [x | maxdiff] pre-split into bf16 hi/lo, [m][256], padded rows for OOB cp.async
__device__ __nv_bfloat16  g_Ah[(size_t)(MAXN + 128) * 256];
__device__ __nv_bfloat16  g_Al[(size_t)(MAXN + 128) * 256];
__device__ __nv_bfloat16  g_Wh[C * 2 * C];   // [n][k], hi
__device__ __nv_bfloat16  g_Wl[C * 2 * C];   // [n][k], lo

__device__ __forceinline__ uint32_t bits2(__nv_bfloat162 v) {
    return *(uint32_t*)&v;
}

// ---------------------------------------------------------------------------
// Front-end kernels
// ---------------------------------------------------------------------------
__global__ void zero_deg_kernel(int n) {
    int i = blockIdx.x * blockDim.x + threadIdx.x;
    if (i < n) g_deg[i] = 0;
}
__global__ void hist_kernel(const int* __restrict__ dst, int E) {
    int e = blockIdx.x * blockDim.x + threadIdx.x;
    if (e < E) atomicAdd(&g_deg[dst[e]], 1);
}
__global__ void scan_kernel(int n) {
    __shared__ int sums[1024];
    int t = threadIdx.x;
    int chunk = (n + 1023) / 1024;
    int lo = t * chunk, hi = min(lo + chunk, n);
    int s = 0;
    for (int i = lo; i < hi; i++) s += g_deg[i];
    sums[t] = s;
    __syncthreads();
    for (int off = 1; off < 1024; off <<= 1) {
        int v = (t >= off) ? sums[t - off] : 0;
        __syncthreads();
        sums[t] += v;
        __syncthreads();
    }
    int excl = (t == 0) ? 0 : sums[t - 1];
    for (int i = lo; i < hi; i++) {
        int d = g_deg[i];
        g_off[i] = excl;
        g_cursor[i] = excl;
        excl += d;
    }
    if (t == 1023) g_off[n] = excl;
}
__global__ void scatter_kernel(const int* __restrict__ src,
                               const int* __restrict__ dst, int E) {
    int e = blockIdx.x * blockDim.x + threadIdx.x;
    if (e < E) {
        int d = dst[e];
        int pos = atomicAdd(&g_cursor[d], 1);
        g_csr_src[pos] = src[e];
    }
}

// x -> bf16 hi/lo into A columns [0,128)
__global__ void xsplit_kernel(const float* __restrict__ x, int N) {
    int i = blockIdx.x * blockDim.x + threadIdx.x;   // float4 index
    if (i < N * 32) {
        float4 v = __ldg((const float4*)x + i);
        int m = i >> 5, kq = (i & 31) * 4;
        __nv_bfloat162 h01 = __floats2bfloat162_rn(v.x, v.y);
        __nv_bfloat162 h23 = __floats2bfloat162_rn(v.z, v.w);
        __nv_bfloat162 l01 = __floats2bfloat162_rn(
            v.x - __bfloat162float(__low2bfloat16(h01)),
            v.y - __bfloat162float(__high2bfloat16(h01)));
        __nv_bfloat162 l23 = __floats2bfloat162_rn(
            v.z - __bfloat162float(__low2bfloat16(h23)),
            v.w - __bfloat162float(__high2bfloat16(h23)));
        size_t o = (size_t)m * 256 + kq;
        *(uint2*)(g_Ah + o) = make_uint2(bits2(h01), bits2(h23));
        *(uint2*)(g_Al + o) = make_uint2(bits2(l01), bits2(l23));
    }
}

// segment-min gather + maxdiff, split straight to bf16 hi/lo cols [128,256)
__global__ void aggregate_kernel(const float* __restrict__ x, int N) {
    int node = blockIdx.x * 8 + (threadIdx.x >> 5);
    if (node >= N) return;
    int lane = threadIdx.x & 31;
    int begin = g_off[node], end = g_off[node + 1];
    const float INF = __int_as_float(0x7F800000);
    float4 mn = make_float4(INF, INF, INF, INF);
    int j = begin;
    for (; j + 4 <= end; j += 4) {
        int s0 = __ldg(g_csr_src + j + 0);
        int s1 = __ldg(g_csr_src + j + 1);
        int s2 = __ldg(g_csr_src + j + 2);
        int s3 = __ldg(g_csr_src + j + 3);
        float4 a0 = __ldg((const float4*)(x + (size_t)s0 * C) + lane);
        float4 a1 = __ldg((const float4*)(x + (size_t)s1 * C) + lane);
        float4 a2 = __ldg((const float4*)(x + (size_t)s2 * C) + lane);
        float4 a3 = __ldg((const float4*)(x + (size_t)s3 * C) + lane);
        mn.x = fminf(mn.x, fminf(fminf(a0.x, a1.x), fminf(a2.x, a3.x)));
        mn.y = fminf(mn.y, fminf(fminf(a0.y, a1.y), fminf(a2.y, a3.y)));
        mn.z = fminf(mn.z, fminf(fminf(a0.z, a1.z), fminf(a2.z, a3.z)));
        mn.w = fminf(mn.w, fminf(fminf(a0.w, a1.w), fminf(a2.w, a3.w)));
    }
    for (; j < end; j++) {
        int s0 = __ldg(g_csr_src + j);
        float4 a0 = __ldg((const float4*)(x + (size_t)s0 * C) + lane);
        mn.x = fminf(mn.x, a0.x); mn.y = fminf(mn.y, a0.y);
        mn.z = fminf(mn.z, a0.z); mn.w = fminf(mn.w, a0.w);
    }
    float4 md = make_float4(0.f, 0.f, 0.f, 0.f);
    if (end > begin) {
        float4 xd = __ldg((const float4*)(x + (size_t)node * C) + lane);
        md = make_float4(xd.x - mn.x, xd.y - mn.y, xd.z - mn.z, xd.w - mn.w);
    }
    __nv_bfloat162 h01 = __floats2bfloat162_rn(md.x, md.y);
    __nv_bfloat162 h23 = __floats2bfloat162_rn(md.z, md.w);
    __nv_bfloat162 l01 = __floats2bfloat162_rn(
        md.x - __bfloat162float(__low2bfloat16(h01)),
        md.y - __bfloat162float(__high2bfloat16(h01)));
    __nv_bfloat162 l23 = __floats2bfloat162_rn(
        md.z - __bfloat162float(__low2bfloat16(h23)),
        md.w - __bfloat162float(__high2bfloat16(h23)));
    size_t o = (size_t)node * 256 + 128 + lane * 4;
    *(uint2*)(g_Ah + o) = make_uint2(bits2(h01), bits2(h23));
    *(uint2*)(g_Al + o) = make_uint2(bits2(l01), bits2(l23));
}

__global__ void wsplit_kernel(const float* __restrict__ W) {
    int idx = blockIdx.x * blockDim.x + threadIdx.x;
    if (idx < 2 * C * C) {
        int k = idx >> 7, n = idx & 127;
        float v = __ldg(W + idx);
        __nv_bfloat16 hi = __float2bfloat16(v);
        __nv_bfloat16 lo = __float2bfloat16(v - __bfloat162float(hi));
        g_Wh[n * 256 + k] = hi;
        g_Wl[n * 256 + k] = lo;
    }
}

// ---------------------------------------------------------------------------
// GEMM: out = relu(A @ W + b), A bf16 hi/lo pre-split.
// CTA 128x128, K=256 in 8 chunks of 32, cp.async double buffer, ldmatrix.
// 8 warps = 4(M) x 2(N), warp tile 32x64.
// ---------------------------------------------------------------------------
#define BSTR  80                     // smem bytes per 32-k row (64B data + 16B pad)
#define OA_HI 0
#define OA_LO 10240
#define OB_HI 20480
#define OB_LO 30720
#define BUFSZ 40960
#define SMEM_TOTAL (2 * BUFSZ)       // 81920

__device__ __forceinline__ uint32_t smem_u32(const void* p) {
    uint32_t a;
    asm("{ .reg .u64 t; cvta.to.shared.u64 t, %1; cvt.u32.u64 %0, t; }" : "=r"(a) : "l"(p));
    return a;
}
__device__ __forceinline__ void mma_bf16(float* d, const uint32_t* a,
                                         uint32_t b0, uint32_t b1) {
    asm volatile(
        "mma.sync.aligned.m16n8k16.row.col.f32.bf16.bf16.f32 "
        "{%0,%1,%2,%3}, {%4,%5,%6,%7}, {%8,%9}, {%0,%1,%2,%3};"
        : "+f"(d[0]), "+f"(d[1]), "+f"(d[2]), "+f"(d[3])
        : "r"(a[0]), "r"(a[1]), "r"(a[2]), "r"(a[3]), "r"(b0), "r"(b1));
}
__device__ __forceinline__ void ldsm_x4(uint32_t* r, uint32_t addr) {
    asm volatile("ldmatrix.sync.aligned.m8n8.x4.shared.b16 {%0,%1,%2,%3}, [%4];"
        : "=r"(r[0]), "=r"(r[1]), "=r"(r[2]), "=r"(r[3]) : "r"(addr));
}
__device__ __forceinline__ void ldsm_x2(uint32_t* r, uint32_t addr) {
    asm volatile("ldmatrix.sync.aligned.m8n8.x2.shared.b16 {%0,%1}, [%2];"
        : "=r"(r[0]), "=r"(r[1]) : "r"(addr));
}
__device__ __forceinline__ void cp16(uint32_t dst, const void* src) {
    asm volatile("cp.async.cg.shared.global [%0], [%1], 16;" :: "r"(dst), "l"(src) : "memory");
}

__device__ __forceinline__ void load_chunk(uint32_t sbuf, int ch, int m0, int t) {
#pragma unroll
    for (int i = 0; i < 4; i++) {           // A: 128 rows x 4 segs x 2 arrays
        int f   = t + i * 256;              // 0..1023
        int row = f >> 3;
        int u   = f & 7;
        int seg = u & 3;
        int hl  = u >> 2;
        const __nv_bfloat16* g = hl ? g_Al : g_Ah;
        const void* src = g + (size_t)(m0 + row) * 256 + ch * 32 + seg * 8;
        cp16(sbuf + (hl ? OA_LO : OA_HI) + row * BSTR + seg * 16, src);
    }
#pragma unroll
    for (int i = 0; i < 4; i++) {           // B: 128 n-rows x 4 segs x 2 arrays
        int f   = t + i * 256;
        int n   = f >> 3;
        int u   = f & 7;
        int seg = u & 3;
        int hl  = u >> 2;
        const __nv_bfloat16* g = hl ? g_Wl : g_Wh;
        const void* src = g + (size_t)n * 256 + ch * 32 + seg * 8;
        cp16(sbuf + (hl ? OB_LO : OB_HI) + n * BSTR + seg * 16, src);
    }
}

__global__ void __launch_bounds__(256, 2)
gemm_mma_kernel(const float* __restrict__ bias,
                float* __restrict__ out,
                int N) {
    extern __shared__ char smem[];
    uint32_t sb = smem_u32(smem);
    int t    = threadIdx.x;
    int wid  = t >> 5;
    int lane = t & 31;
    int wm   = wid >> 1;          // 0..3
    int wn   = wid & 1;           // 0..1
    int m0   = blockIdx.x * 128;
    int mrow = lane >> 2;

    // ldmatrix lane-address components
    int trow = lane & 7;
    int tl4  = lane >> 3;                 // 0..3
    int a_roff = (tl4 & 1) * 8;           // tile order: (r0,k0)(r8,k0)(r0,k8)(r8,k8)
    int a_koff = (tl4 >> 1) * 8;
    int b_koff = ((lane >> 3) & 1) * 8;   // x2: lanes 0-15 matter

    float acc[2][8][4];
#pragma unroll
    for (int mt = 0; mt < 2; mt++)
#pragma unroll
        for (int nt = 0; nt < 8; nt++)
#pragma unroll
            for (int j = 0; j < 4; j++) acc[mt][nt][j] = 0.0f;

    load_chunk(sb, 0, m0, t);
    asm volatile("cp.async.commit_group;" ::: "memory");
    load_chunk(sb + BUFSZ, 1, m0, t);
    asm volatile("cp.async.commit_group;" ::: "memory");

    for (int ch = 0; ch < 8; ch++) {
        asm volatile("cp.async.wait_group 1;" ::: "memory");
        __syncthreads();
        uint32_t buf = sb + (ch & 1) * BUFSZ;

#pragma unroll
        for (int ks = 0; ks < 2; ks++) {
            uint32_t ah[2][4], al[2][4];
#pragma unroll
            for (int mt = 0; mt < 2; mt++) {
                uint32_t ao = buf + (wm * 32 + mt * 16 + a_roff + trow) * BSTR
                            + (ks * 16 + a_koff) * 2;
                ldsm_x4(ah[mt], ao + OA_HI);
                ldsm_x4(al[mt], ao + OA_LO);
            }
#pragma unroll
            for (int nt = 0; nt < 8; nt++) {
                uint32_t bo = buf + (wn * 64 + nt * 8 + trow) * BSTR
                            + (ks * 16 + b_koff) * 2;
                uint32_t bh[2], bl[2];
                ldsm_x2(bh, bo + OB_HI);
                ldsm_x2(bl, bo + OB_LO);
#pragma unroll
                for (int mt = 0; mt < 2; mt++) {
                    mma_bf16(acc[mt][nt], ah[mt], bh[0], bh[1]);
                    mma_bf16(acc[mt][nt], ah[mt], bl[0], bl[1]);
                    mma_bf16(acc[mt][nt], al[mt], bh[0], bh[1]);
                }
            }
        }
        __syncthreads();
        if (ch < 6) {
            load_chunk(buf, ch + 2, m0, t);
            asm volatile("cp.async.commit_group;" ::: "memory");
        } else {
            asm volatile("cp.async.commit_group;" ::: "memory");  // empty group keeps wait_group math
        }
    }

    // ---- epilogue: bias + relu ----
#pragma unroll
    for (int mt = 0; mt < 2; mt++) {
        int m = m0 + wm * 32 + mt * 16 + mrow;
#pragma unroll
        for (int nt = 0; nt < 8; nt++) {
            int n = wn * 64 + nt * 8 + (lane & 3) * 2;
            float2 bv = __ldg((const float2*)(bias + n));
            if (m < N) {
                float2 o0;
                o0.x = fmaxf(acc[mt][nt][0] + bv.x, 0.f);
                o0.y = fmaxf(acc[mt][nt][1] + bv.y, 0.f);
                *(float2*)(out + (size_t)m * C + n) = o0;
            }
            if (m + 8 < N) {
                float2 o1;
                o1.x = fmaxf(acc[mt][nt][2] + bv.x, 0.f);
                o1.y = fmaxf(acc[mt][nt][3] + bv.y, 0.f);
                *(float2*)(out + (size_t)(m + 8) * C + n) = o1;
            }
        }
    }
}

// ---------------------------------------------------------------------------
// Launch
// ---------------------------------------------------------------------------
extern "C" void kernel_launch(void* const* d_in, const int* in_sizes, int n_in,
                              void* d_out, int out_size) {
    const float* x    = (const float*)d_in[0];
    const float* W    = (const float*)d_in[1];
    const float* bias = (const float*)d_in[2];
    const int*   src  = (const int*)d_in[3];
    const int*   dst  = (const int*)d_in[4];
    float*       out  = (float*)d_out;

    int N = in_sizes[0] / C;   // 100000
    int E = in_sizes[3];       // 1600000

    cudaFuncSetAttribute(gemm_mma_kernel,
                         cudaFuncAttributeMaxDynamicSharedMemorySize, SMEM_TOTAL);

    zero_deg_kernel<<<(N + 255) / 256, 256>>>(N);
    hist_kernel<<<(E + 255) / 256, 256>>>(dst, E);
    scan_kernel<<<1, 1024>>>(N);
    scatter_kernel<<<(E + 255) / 256, 256>>>(src, dst, E);
    wsplit_kernel<<<(2 * C * C + 255) / 256, 256>>>(W);
    xsplit_kernel<<<(N * 32 + 255) / 256, 256>>>(x, N);

    int ablocks = (N + 7) / 8;
    aggregate_kernel<<<ablocks, 256>>>(x, N);

    int gblocks = (N + 127) / 128;   // 782
    gemm_mma_kernel<<<gblocks, 256, SMEM_TOTAL>>>(bias, out, N);
}